// round 15
// baseline (speedup 1.0000x reference)
#include <cuda_runtime.h>
#include <cuda_fp16.h>
#include <cstdint>
#include <cstddef>

// ---------------------------------------------------------------------------
// Problem constants
// ---------------------------------------------------------------------------
#define C_DIM   1024
#define H_HEADS 16
#define D_HEAD  64
#define B_BATCH 2
#define LQ      1024
#define LK      4096

// ---------------------------------------------------------------------------
// Device scratch (allocation-free). All fp16 as unsigned half2 words.
// kperm16 within-16 groups: w0:(j0,j1) w1:(j8,j9) w2:(j2,j3) w3:(j10,j11)
// w4:(j4,j5) w5:(j12,j13) w6:(j6,j7) w7:(j14,j15)  -> fragment pairs adjacent.
// g_x*/g_wt/g_ctx: kperm16 along k/c. g_q/g_k: kperm16 along d.
// g_v: TRANSPOSED [b,h,d,key] with kperm16 along the KEY dim.
// ---------------------------------------------------------------------------
__device__ unsigned g_q  [B_BATCH * H_HEADS * LQ * (D_HEAD / 2)];
__device__ unsigned g_k  [B_BATCH * H_HEADS * LK * (D_HEAD / 2)];
__device__ unsigned g_v  [B_BATCH * H_HEADS * D_HEAD * (LK / 2)];
__device__ unsigned g_ctx[B_BATCH * LQ * (C_DIM / 2)];
__device__ unsigned g_xq [B_BATCH * LQ * (C_DIM / 2)];
__device__ unsigned g_xk [B_BATCH * LK * (C_DIM / 2)];
__device__ unsigned g_xv [B_BATCH * LK * (C_DIM / 2)];
__device__ unsigned g_wt [4 * C_DIM * (C_DIM / 2)];

// ---------------------------------------------------------------------------
// Helpers
// ---------------------------------------------------------------------------
__device__ __forceinline__ unsigned f2h2(float lo, float hi) {
    __half2 h = __floats2half2_rn(lo, hi);
    return *reinterpret_cast<unsigned*>(&h);
}
__device__ __forceinline__ float ex2f(float x) {
    float y;
    asm volatile("ex2.approx.f32 %0, %1;" : "=f"(y) : "f"(x));
    return y;
}
// half2-word index (within a 16-elem group row) for even element d
__device__ __forceinline__ int kp16_word(int d) {
    return ((d >> 4) << 3) + 2 * ((d & 7) >> 1) + ((d >> 3) & 1);
}
// permuted half position for element j under kperm16 (within full row)
__device__ __forceinline__ int kp16_pos(int j) {
    int g = j & ~15;
    int p = j & 15;
    int w = 2 * ((p & 7) >> 1) + ((p >> 3) & 1);
    return g + 2 * w + (p & 1);
}
// D(16x8,f32) += A(16x16 f16 row) * B(16x8 f16 col)
__device__ __forceinline__ void mma_f16(float c[4], const unsigned a[4], const unsigned b[2]) {
    asm volatile(
        "mma.sync.aligned.m16n8k16.row.col.f32.f16.f16.f32 "
        "{%0,%1,%2,%3}, {%4,%5,%6,%7}, {%8,%9}, {%0,%1,%2,%3};"
        : "+f"(c[0]), "+f"(c[1]), "+f"(c[2]), "+f"(c[3])
        : "r"(a[0]), "r"(a[1]), "r"(a[2]), "r"(a[3]), "r"(b[0]), "r"(b[1]));
}
__device__ __forceinline__ void cp_async16(void* smem, const void* gmem) {
    unsigned sa = (unsigned)__cvta_generic_to_shared(smem);
    asm volatile("cp.async.ca.shared.global [%0], [%1], 16;" :: "r"(sa), "l"(gmem));
}
__device__ __forceinline__ void cp_commit() { asm volatile("cp.async.commit_group;"); }
template <int N>
__device__ __forceinline__ void cp_wait() { asm volatile("cp.async.wait_group %0;" :: "n"(N)); }

// ---------------------------------------------------------------------------
// Pre-convert: fp32 -> fp16, kperm16-packed. One thread per 16-float group.
// ---------------------------------------------------------------------------
#define G16_Q (B_BATCH * LQ * C_DIM / 16)
#define G16_K (B_BATCH * LK * C_DIM / 16)
#define G16_W (C_DIM * C_DIM / 16)

__global__ __launch_bounds__(512)
void precvt_kernel(const float4* __restrict__ Q, const float4* __restrict__ K,
                   const float4* __restrict__ V, const float4* __restrict__ Wq,
                   const float4* __restrict__ Wk, const float4* __restrict__ Wv,
                   const float4* __restrict__ Wo)
{
    const int total = G16_Q + 2 * G16_K + 4 * G16_W;
    for (int g = blockIdx.x * blockDim.x + threadIdx.x; g < total;
         g += gridDim.x * blockDim.x) {
        const float4* s;
        unsigned* d;
        int j = g;
        if (j < G16_Q)                 { s = Q; d = g_xq; }
        else if ((j -= G16_Q) < G16_K) { s = K; d = g_xk; }
        else if ((j -= G16_K) < G16_K) { s = V; d = g_xv; }
        else {
            j -= G16_K;
            int w = j / G16_W;
            j -= w * G16_W;
            s = (w == 0) ? Wq : (w == 1) ? Wk : (w == 2) ? Wv : Wo;
            d = g_wt + (size_t)w * (C_DIM * (C_DIM / 2));
        }
        const float4* f4 = s + (size_t)j * 4;
        float4 F0 = f4[0], F1 = f4[1], F2 = f4[2], F3 = f4[3];
        uint4 u0, u1;
        u0.x = f2h2(F0.x, F0.y);
        u0.y = f2h2(F2.x, F2.y);
        u0.z = f2h2(F0.z, F0.w);
        u0.w = f2h2(F2.z, F2.w);
        u1.x = f2h2(F1.x, F1.y);
        u1.y = f2h2(F3.x, F3.y);
        u1.z = f2h2(F1.z, F1.w);
        u1.w = f2h2(F3.z, F3.w);
        uint4* dst = (uint4*)d;
        dst[2 * (size_t)j]     = u0;
        dst[2 * (size_t)j + 1] = u1;
    }
}

// ---------------------------------------------------------------------------
// FP16 GEMM body (R11-proven). BK=32 halves (2 k16 MMA steps per tile,
// NK=32), 3-stage cp.async ring, proven wait schedule.
// BM=BN=128, 256 thr (8 warps 2x4), warp tile 64x32, 2 CTAs/SM.
// MODE 0: fp32 [M,C]. MODE 1: head-split kperm16 (g_q/g_k).
// MODE 2: head-split transposed [b,h,d,key], KEY dim kperm16 (g_v).
// ---------------------------------------------------------------------------
#define KSTRW 20                      // words per row (16 data + 4 pad)
#define STAGEW (128 * KSTRW)          // 2560 words per matrix stage
#define GEMM_SMEM_BYTES (3 * 2 * STAGEW * 4)   // 61,440 B

__device__ __forceinline__ void gemm_load_stage(
    unsigned* sA, unsigned* sB, const unsigned* __restrict__ X,
    const unsigned* __restrict__ W, int bm, int bn, int kt, int tid)
{
#pragma unroll
    for (int it = 0; it < 2; it++) {
        int f   = tid + it * 256;       // 0..511
        int row = f >> 2;               // 0..127
        int seg = (f & 3) * 4;          // word offset 0,4,8,12
        cp_async16(&sA[row * KSTRW + seg], &X[(size_t)(bm + row) * 512 + kt * 16 + seg]);
        cp_async16(&sB[row * KSTRW + seg], &W[(size_t)(bn + row) * 512 + kt * 16 + seg]);
    }
    cp_commit();
}

template <int MODE>
__device__ __forceinline__ void gemm_body(
    const unsigned* __restrict__ X, const unsigned* __restrict__ W,
    const float* __restrict__ bias, void* __restrict__ out,
    int Lrows, int bm, int bn, unsigned* gsm)
{
    unsigned* sAr = gsm;
    unsigned* sBr = gsm + 3 * STAGEW;

    const int tid  = threadIdx.x;
    const int wid  = tid >> 5;
    const int lane = tid & 31;
    const int wm   = (wid & 1) * 64;
    const int wn   = (wid >> 1) * 32;
    const int qr   = lane >> 2;
    const int ql   = lane & 3;

    float acc[4][4][4];
#pragma unroll
    for (int i = 0; i < 4; i++)
#pragma unroll
        for (int j = 0; j < 4; j++)
#pragma unroll
            for (int r = 0; r < 4; r++) acc[i][j][r] = 0.f;

    const int NK = C_DIM / 32;  // 32 k-tiles

    gemm_load_stage(sAr, sBr, X, W, bm, bn, 0, tid);
    gemm_load_stage(sAr + STAGEW, sBr + STAGEW, X, W, bm, bn, 1, tid);

    for (int kt = 0; kt < NK; kt++) {
        // Pending ⊆ {kt, kt+1}: wait until <=1 remains -> kt landed.
        if (kt + 1 < NK) cp_wait<1>(); else cp_wait<0>();
        __syncthreads();

        const int buf = kt % 3;
        if (kt + 2 < NK) {
            const int nb = (kt + 2) % 3;
            gemm_load_stage(sAr + nb * STAGEW, sBr + nb * STAGEW,
                            X, W, bm, bn, kt + 2, tid);
        }

        const unsigned* sA = sAr + buf * STAGEW;
        const unsigned* sB = sBr + buf * STAGEW;

#pragma unroll
        for (int ks = 0; ks < 2; ks++) {
            const int kwb = ks * 8;     // word base of this k16 step
            unsigned af[4][4], bf[4][2];
#pragma unroll
            for (int mi = 0; mi < 4; mi++) {
                int r0 = wm + mi * 16 + qr;
                uint2 lo = *(const uint2*)&sA[(r0)     * KSTRW + kwb + 2 * ql];
                uint2 hi = *(const uint2*)&sA[(r0 + 8) * KSTRW + kwb + 2 * ql];
                af[mi][0] = lo.x;
                af[mi][1] = hi.x;
                af[mi][2] = lo.y;
                af[mi][3] = hi.y;
            }
#pragma unroll
            for (int ni = 0; ni < 4; ni++) {
                int c0 = wn + ni * 8 + qr;
                uint2 bb = *(const uint2*)&sB[c0 * KSTRW + kwb + 2 * ql];
                bf[ni][0] = bb.x;
                bf[ni][1] = bb.y;
            }
#pragma unroll
            for (int mi = 0; mi < 4; mi++)
#pragma unroll
                for (int ni = 0; ni < 4; ni++)
                    mma_f16(acc[mi][ni], af[mi], bf[ni]);
        }
    }

    // ---- Epilogue ----
    if (MODE == 2) __syncthreads();   // gsm reused as transpose buffer
    __half* sT = (__half*)gsm;        // [128 dcol][136] halves (MODE 2)

#pragma unroll
    for (int mi = 0; mi < 4; mi++) {
#pragma unroll
        for (int ni = 0; ni < 4; ni++) {
            const int m0 = bm + wm + mi * 16 + qr;
            const int n0 = bn + wn + ni * 8 + 2 * ql;
            const float b0 = bias[n0], b1 = bias[n0 + 1];
            const float v00 = acc[mi][ni][0] + b0;
            const float v01 = acc[mi][ni][1] + b1;
            const float v10 = acc[mi][ni][2] + b0;
            const float v11 = acc[mi][ni][3] + b1;
            if (MODE == 0) {
                float* op = (float*)out;
                op[(size_t)m0 * C_DIM + n0]           = v00;
                op[(size_t)m0 * C_DIM + n0 + 1]       = v01;
                op[(size_t)(m0 + 8) * C_DIM + n0]     = v10;
                op[(size_t)(m0 + 8) * C_DIM + n0 + 1] = v11;
            } else if (MODE == 1) {
                unsigned* op = (unsigned*)out;
                const int h   = n0 >> 6;
                const int d   = n0 & 63;
                const int wrd = kp16_word(d);
                const int bz  = m0 / Lrows;
                const int l   = m0 - bz * Lrows;
                op[(((size_t)(bz * H_HEADS + h) * Lrows) + l) * 32 + wrd] = f2h2(v00, v01);
                const int bz2 = (m0 + 8) / Lrows;
                const int l2  = (m0 + 8) - bz2 * Lrows;
                op[(((size_t)(bz2 * H_HEADS + h) * Lrows) + l2) * 32 + wrd] = f2h2(v10, v11);
            } else {
                // MODE 2: stage into [dcol][key] with kperm16 on the key index
                const int jc = wn + ni * 8 + 2 * ql;
                const int kl = wm + mi * 16 + qr;
                sT[(jc)     * 136 + kp16_pos(kl)]     = __float2half_rn(v00);
                sT[(jc + 1) * 136 + kp16_pos(kl)]     = __float2half_rn(v01);
                sT[(jc)     * 136 + kp16_pos(kl + 8)] = __float2half_rn(v10);
                sT[(jc + 1) * 136 + kp16_pos(kl + 8)] = __float2half_rn(v11);
            }
        }
    }

    if (MODE == 2) {
        __syncthreads();
        const int bz = bm / Lrows;           // Lrows == LK
        const int l0 = bm - bz * Lrows;
        unsigned* op = (unsigned*)out;
#pragma unroll
        for (int p = 0; p < 8; p++) {
            int c   = tid + p * 256;          // 0..2047
            int j   = c >> 4;                 // local d col
            int seg = c & 15;                 // 16 uint4 per 128-key row
            uint4 v = *(const uint4*)&sT[j * 136 + seg * 8];
            size_t dstw = (size_t)(bz * 1024 + bn + j) * (LK / 2) + (l0 >> 1) + seg * 4;
            *(uint4*)&op[dstw] = v;
        }
    }
}

// Fused Q/K/V projections: 1152 CTA tiles.
__global__ __launch_bounds__(256, 2)
void qkv_proj_kernel(const float* __restrict__ Wq_b, const float* __restrict__ Wk_b,
                     const float* __restrict__ Wv_b)
{
    extern __shared__ unsigned gsm[];
    int t = blockIdx.x;
    if (t < 512) {
        const int bm = (t >> 3) * 128, bn = (t & 7) * 128;
        gemm_body<1>(g_xk, g_wt + 1 * C_DIM * (C_DIM / 2), Wk_b, g_k, LK, bm, bn, gsm);
    } else if (t < 1024) {
        t -= 512;
        const int bm = (t >> 3) * 128, bn = (t & 7) * 128;
        gemm_body<2>(g_xv, g_wt + 2 * C_DIM * (C_DIM / 2), Wv_b, g_v, LK, bm, bn, gsm);
    } else {
        t -= 1024;
        const int bm = (t >> 3) * 128, bn = (t & 7) * 128;
        gemm_body<1>(g_xq, g_wt, Wq_b, g_q, LQ, bm, bn, gsm);
    }
}

__global__ __launch_bounds__(256, 2)
void oproj_kernel(const float* __restrict__ Wo_b, float* __restrict__ out)
{
    extern __shared__ unsigned gsm[];
    const int bm = blockIdx.y * 128;
    const int bn = blockIdx.x * 128;
    gemm_body<0>(g_ctx, g_wt + 3 * C_DIM * (C_DIM / 2), Wo_b, out, 1, bm, bn, gsm);
}

// ---------------------------------------------------------------------------
// Flash attention (fp16, R11-proven pipeline). Q/K kperm16 d -> LDS.64 frags.
// V transposed [d][key] with kperm16 keys -> PV B-frags are single LDS.64
// (the ONLY change vs the 440us R11 kernel). f32-exp softmax; P packed to
// half2 as the PV A-fragments. 2 CTAs/SM, 4 syncs/chunk.
// ---------------------------------------------------------------------------
#define QT 128
#define KCH 64
#define QSTRW 36    // words/row (32 data + 4 pad); conflict-free frag loads
#define FLASH_SMEM_WORDS (QT * QSTRW + KCH * QSTRW + D_HEAD * QSTRW + KCH)
#define FLASH_SMEM_BYTES (FLASH_SMEM_WORDS * 4)   // 37,120 B
#define LOG2E 1.4426950408889634f

__global__ __launch_bounds__(256, 2)
void flash_kernel(const float* __restrict__ biasAll)
{
    extern __shared__ unsigned smu[];
    unsigned* uQ    = smu;                        // [128 q][36w]
    unsigned* uK    = uQ + QT * QSTRW;            // [64 key][36w]
    unsigned* uV    = uK + KCH * QSTRW;           // [64 d][36w] key-permuted
    float*    fBias = (float*)(uV + D_HEAD * QSTRW);  // [64]

    const int tid  = threadIdx.x;
    const int w    = tid >> 5;
    const int lane = tid & 31;
    const int qr   = lane >> 2;
    const int ql   = lane & 3;
    const int q0   = blockIdx.x * QT;
    const int h    = blockIdx.y;
    const int b    = blockIdx.z;

    const unsigned* qp = g_q + (size_t)(b * H_HEADS + h) * LQ * 32;
    const unsigned* kp = g_k + (size_t)(b * H_HEADS + h) * LK * 32;
    const unsigned* vp = g_v + (size_t)(b * H_HEADS + h) * D_HEAD * (LK / 2);
    const float*    bp = biasAll + (size_t)b * LK;

    // ---- prologue: group A = {Q, K0, bias0}; group B = {V0} ----
#pragma unroll
    for (int it = 0; it < 4; it++) {
        int f = tid + it * 256;
        int row = f >> 3;
        int seg = (f & 7) * 4;
        cp_async16(&uQ[row * QSTRW + seg], &qp[(size_t)(q0 + row) * 32 + seg]);
    }
#pragma unroll
    for (int it = 0; it < 2; it++) {
        int f = tid + it * 256;
        int row = f >> 3;
        int seg = (f & 7) * 4;
        cp_async16(&uK[row * QSTRW + seg], &kp[(size_t)row * 32 + seg]);
    }
    if (tid < 16) cp_async16(&fBias[tid * 4], &bp[tid * 4]);
    cp_commit();
#pragma unroll
    for (int it = 0; it < 2; it++) {
        int f = tid + it * 256;
        int d = f >> 3;
        int seg = (f & 7) * 4;
        cp_async16(&uV[d * QSTRW + seg], &vp[(size_t)d * (LK / 2) + seg]);
    }
    cp_commit();

    float o[8][4];
#pragma unroll
    for (int ni = 0; ni < 8; ni++)
#pragma unroll
        for (int r = 0; r < 4; r++) o[ni][r] = 0.f;

    float row_m[2] = {-1e30f, -1e30f};
    float row_l[2] = {0.f, 0.f};
    const float scl = 0.125f * LOG2E;
    const int r0 = w * 16 + qr;

    const int NCH = LK / KCH;  // 64
    for (int i = 0; i < NCH; i++) {
        const int kc0 = i * KCH;

        cp_wait<1>();   // pending {K_i, V_i} -> K_i (+Q,bias) landed
        if (tid < 16) {
            float4 bv = *(float4*)&fBias[tid * 4];
            bv.x *= LOG2E; bv.y *= LOG2E; bv.z *= LOG2E; bv.w *= LOG2E;
            *(float4*)&fBias[tid * 4] = bv;
        }
        __syncthreads();   // #1: K + bias visible

        // ---- S = Q @ K^T ----
        float s[8][4];
#pragma unroll
        for (int ni = 0; ni < 8; ni++)
#pragma unroll
            for (int r = 0; r < 4; r++) s[ni][r] = 0.f;

#pragma unroll
        for (int kk = 0; kk < 4; kk++) {
            const int kwb = kk * 8;
            uint2 aLo = *(const uint2*)&uQ[(r0)     * QSTRW + kwb + 2 * ql];
            uint2 aHi = *(const uint2*)&uQ[(r0 + 8) * QSTRW + kwb + 2 * ql];
            unsigned af[4];
            af[0] = aLo.x;
            af[1] = aHi.x;
            af[2] = aLo.y;
            af[3] = aHi.y;
#pragma unroll
            for (int ni = 0; ni < 8; ni++) {
                uint2 bb = *(const uint2*)&uK[(ni * 8 + qr) * QSTRW + kwb + 2 * ql];
                unsigned bf[2];
                bf[0] = bb.x;
                bf[1] = bb.y;
                mma_f16(s[ni], af, bf);
            }
        }

#pragma unroll
        for (int ni = 0; ni < 8; ni++) {
            const int c0 = ni * 8 + 2 * ql;
            const float b0 = fBias[c0], b1 = fBias[c0 + 1];
            s[ni][0] = fmaf(s[ni][0], scl, b0);
            s[ni][1] = fmaf(s[ni][1], scl, b1);
            s[ni][2] = fmaf(s[ni][2], scl, b0);
            s[ni][3] = fmaf(s[ni][3], scl, b1);
        }
        __syncthreads();   // #2: done with K + bias

        if (i + 1 < NCH) {
#pragma unroll
            for (int it = 0; it < 2; it++) {
                int f = tid + it * 256;
                int row = f >> 3;
                int seg = (f & 7) * 4;
                cp_async16(&uK[row * QSTRW + seg],
                           &kp[(size_t)(kc0 + KCH + row) * 32 + seg]);
            }
            if (tid < 16) cp_async16(&fBias[tid * 4], &bp[kc0 + KCH + tid * 4]);
            cp_commit();
        }

        // ---- online softmax (f32 exp, R11 form) ----
#pragma unroll
        for (int half = 0; half < 2; half++) {
            float mx = -1e30f;
#pragma unroll
            for (int ni = 0; ni < 8; ni++)
                mx = fmaxf(mx, fmaxf(s[ni][2 * half], s[ni][2 * half + 1]));
            mx = fmaxf(mx, __shfl_xor_sync(0xffffffffu, mx, 1));
            mx = fmaxf(mx, __shfl_xor_sync(0xffffffffu, mx, 2));
            const float mnew  = fmaxf(row_m[half], mx);
            const float alpha = ex2f(row_m[half] - mnew);
            row_m[half] = mnew;
            float ls = 0.f;
#pragma unroll
            for (int ni = 0; ni < 8; ni++) {
                float e0 = ex2f(s[ni][2 * half]     - mnew);
                float e1 = ex2f(s[ni][2 * half + 1] - mnew);
                s[ni][2 * half]     = e0;
                s[ni][2 * half + 1] = e1;
                ls += e0 + e1;
            }
            ls += __shfl_xor_sync(0xffffffffu, ls, 1);
            ls += __shfl_xor_sync(0xffffffffu, ls, 2);
            row_l[half] = row_l[half] * alpha + ls;
#pragma unroll
            for (int ni = 0; ni < 8; ni++) {
                o[ni][2 * half]     *= alpha;
                o[ni][2 * half + 1] *= alpha;
            }
        }

        // pending {V_i, K_{i+1}} (or {V_i}) -> V_i landed
        if (i + 1 < NCH) cp_wait<1>(); else cp_wait<0>();
        __syncthreads();   // #3: V visible

        // ---- O += P @ V : key-permuted V -> B-frag is one LDS.64 ----
#pragma unroll
        for (int kk = 0; kk < 4; kk++) {
            unsigned af[4];
            af[0] = f2h2(s[2 * kk][0],     s[2 * kk][1]);
            af[1] = f2h2(s[2 * kk][2],     s[2 * kk][3]);
            af[2] = f2h2(s[2 * kk + 1][0], s[2 * kk + 1][1]);
            af[3] = f2h2(s[2 * kk + 1][2], s[2 * kk + 1][3]);
#pragma unroll
            for (int ni = 0; ni < 8; ni++) {
                uint2 bb = *(const uint2*)&uV[(ni * 8 + qr) * QSTRW + kk * 8 + 2 * ql];
                unsigned bf[2];
                bf[0] = bb.x;
                bf[1] = bb.y;
                mma_f16(o[ni], af, bf);
            }
        }
        __syncthreads();   // #4: done with V

        if (i + 1 < NCH) {
#pragma unroll
            for (int it = 0; it < 2; it++) {
                int f = tid + it * 256;
                int d = f >> 3;
                int seg = (f & 7) * 4;
                cp_async16(&uV[d * QSTRW + seg],
                           &vp[(size_t)d * (LK / 2) + ((kc0 + KCH) >> 1) + seg]);
            }
            cp_commit();
        }
    }

    // ---- normalize; write ctx fp16 kperm16-packed ----
    const float inv0 = __fdividef(1.f, row_l[0]);
    const float inv1 = __fdividef(1.f, row_l[1]);
    unsigned* ctx = g_ctx + (size_t)b * LQ * 512;
    const int rA = q0 + r0;
#pragma unroll
    for (int ni = 0; ni < 8; ni++) {
        const int col = h * 64 + ni * 8 + 2 * ql;
        const int wrd = kp16_word(col & 15) + ((col >> 4) << 3);
        ctx[(size_t)rA * 512 + wrd]       = f2h2(o[ni][0] * inv0, o[ni][1] * inv0);
        ctx[(size_t)(rA + 8) * 512 + wrd] = f2h2(o[ni][2] * inv1, o[ni][3] * inv1);
    }
}

// ---------------------------------------------------------------------------
// kernel_launch: 4 stream-ordered launches (graph-capturable, alloc-free)
// ---------------------------------------------------------------------------
extern "C" void kernel_launch(void* const* d_in, const int* in_sizes, int n_in,
                              void* d_out, int out_size)
{
    const float* Q      = (const float*)d_in[0];
    const float* K_in   = (const float*)d_in[1];
    const float* V_in   = (const float*)d_in[2];
    const float* V_bias = (const float*)d_in[3];
    const float* Wq_b   = (const float*)d_in[5];
    const float* Wk_b   = (const float*)d_in[7];
    const float* Wv_b   = (const float*)d_in[9];
    const float* Wo_b   = (const float*)d_in[11];

    cudaFuncSetAttribute(flash_kernel,
                         cudaFuncAttributeMaxDynamicSharedMemorySize, FLASH_SMEM_BYTES);
    cudaFuncSetAttribute(qkv_proj_kernel,
                         cudaFuncAttributeMaxDynamicSharedMemorySize, GEMM_SMEM_BYTES);
    cudaFuncSetAttribute(oproj_kernel,
                         cudaFuncAttributeMaxDynamicSharedMemorySize, GEMM_SMEM_BYTES);

    precvt_kernel<<<1184, 512>>>((const float4*)Q, (const float4*)K_in,
                                 (const float4*)V_in, (const float4*)d_in[4],
                                 (const float4*)d_in[6], (const float4*)d_in[8],
                                 (const float4*)d_in[10]);

    qkv_proj_kernel<<<1152, 256, GEMM_SMEM_BYTES>>>(Wq_b, Wk_b, Wv_b);

    flash_kernel<<<dim3(LQ / QT, H_HEADS, B_BATCH), 256, FLASH_SMEM_BYTES>>>(V_bias);

    oproj_kernel<<<dim3(C_DIM / 128, (B_BATCH * LQ) / 128), 256, GEMM_SMEM_BYTES>>>(
        Wo_b, (float*)d_out);
}

// round 16
// speedup vs baseline: 1.2788x; 1.2788x over previous
#include <cuda_runtime.h>
#include <cuda_fp16.h>
#include <cstdint>
#include <cstddef>

// ---------------------------------------------------------------------------
// Problem constants
// ---------------------------------------------------------------------------
#define C_DIM   1024
#define H_HEADS 16
#define D_HEAD  64
#define B_BATCH 2
#define LQ      1024
#define LK      4096

// ---------------------------------------------------------------------------
// Device scratch (allocation-free). All fp16 as unsigned half2 words.
// kperm16 within-16 groups: w0:(j0,j1) w1:(j8,j9) w2:(j2,j3) w3:(j10,j11)
// w4:(j4,j5) w5:(j12,j13) w6:(j6,j7) w7:(j14,j15)  -> fragment pairs adjacent.
// g_x*/g_wt/g_ctx: kperm16 along k/c. g_q/g_k: kperm16 along d.
// g_v: TRANSPOSED [b,h,d,key] with kperm16 along the KEY dim.
// ---------------------------------------------------------------------------
__device__ unsigned g_q  [B_BATCH * H_HEADS * LQ * (D_HEAD / 2)];
__device__ unsigned g_k  [B_BATCH * H_HEADS * LK * (D_HEAD / 2)];
__device__ unsigned g_v  [B_BATCH * H_HEADS * D_HEAD * (LK / 2)];
__device__ unsigned g_ctx[B_BATCH * LQ * (C_DIM / 2)];
__device__ unsigned g_xq [B_BATCH * LQ * (C_DIM / 2)];
__device__ unsigned g_xk [B_BATCH * LK * (C_DIM / 2)];
__device__ unsigned g_xv [B_BATCH * LK * (C_DIM / 2)];
__device__ unsigned g_wt [4 * C_DIM * (C_DIM / 2)];

// ---------------------------------------------------------------------------
// Helpers
// ---------------------------------------------------------------------------
__device__ __forceinline__ unsigned f2h2(float lo, float hi) {
    __half2 h = __floats2half2_rn(lo, hi);
    return *reinterpret_cast<unsigned*>(&h);
}
__device__ __forceinline__ float ex2f(float x) {
    float y;
    asm volatile("ex2.approx.f32 %0, %1;" : "=f"(y) : "f"(x));
    return y;
}
// half2-word index (within a 16-elem group row) for even element d
__device__ __forceinline__ int kp16_word(int d) {
    return ((d >> 4) << 3) + 2 * ((d & 7) >> 1) + ((d >> 3) & 1);
}
// permuted half position for element j under kperm16 (within full row)
__device__ __forceinline__ int kp16_pos(int j) {
    int g = j & ~15;
    int p = j & 15;
    int w = 2 * ((p & 7) >> 1) + ((p >> 3) & 1);
    return g + 2 * w + (p & 1);
}
// D(16x8,f32) += A(16x16 f16 row) * B(16x8 f16 col)
__device__ __forceinline__ void mma_f16(float c[4], const unsigned a[4], const unsigned b[2]) {
    asm volatile(
        "mma.sync.aligned.m16n8k16.row.col.f32.f16.f16.f32 "
        "{%0,%1,%2,%3}, {%4,%5,%6,%7}, {%8,%9}, {%0,%1,%2,%3};"
        : "+f"(c[0]), "+f"(c[1]), "+f"(c[2]), "+f"(c[3])
        : "r"(a[0]), "r"(a[1]), "r"(a[2]), "r"(a[3]), "r"(b[0]), "r"(b[1]));
}
__device__ __forceinline__ void cp_async16(void* smem, const void* gmem) {
    unsigned sa = (unsigned)__cvta_generic_to_shared(smem);
    asm volatile("cp.async.ca.shared.global [%0], [%1], 16;" :: "r"(sa), "l"(gmem));
}
__device__ __forceinline__ void cp_commit() { asm volatile("cp.async.commit_group;"); }
template <int N>
__device__ __forceinline__ void cp_wait() { asm volatile("cp.async.wait_group %0;" :: "n"(N)); }

// ---------------------------------------------------------------------------
// Pre-convert: fp32 -> fp16, kperm16-packed. One thread per 16-float group.
// ---------------------------------------------------------------------------
#define G16_Q (B_BATCH * LQ * C_DIM / 16)
#define G16_K (B_BATCH * LK * C_DIM / 16)
#define G16_W (C_DIM * C_DIM / 16)

__global__ __launch_bounds__(512)
void precvt_kernel(const float4* __restrict__ Q, const float4* __restrict__ K,
                   const float4* __restrict__ V, const float4* __restrict__ Wq,
                   const float4* __restrict__ Wk, const float4* __restrict__ Wv,
                   const float4* __restrict__ Wo)
{
    const int total = G16_Q + 2 * G16_K + 4 * G16_W;
    for (int g = blockIdx.x * blockDim.x + threadIdx.x; g < total;
         g += gridDim.x * blockDim.x) {
        const float4* s;
        unsigned* d;
        int j = g;
        if (j < G16_Q)                 { s = Q; d = g_xq; }
        else if ((j -= G16_Q) < G16_K) { s = K; d = g_xk; }
        else if ((j -= G16_K) < G16_K) { s = V; d = g_xv; }
        else {
            j -= G16_K;
            int w = j / G16_W;
            j -= w * G16_W;
            s = (w == 0) ? Wq : (w == 1) ? Wk : (w == 2) ? Wv : Wo;
            d = g_wt + (size_t)w * (C_DIM * (C_DIM / 2));
        }
        const float4* f4 = s + (size_t)j * 4;
        float4 F0 = f4[0], F1 = f4[1], F2 = f4[2], F3 = f4[3];
        uint4 u0, u1;
        u0.x = f2h2(F0.x, F0.y);
        u0.y = f2h2(F2.x, F2.y);
        u0.z = f2h2(F0.z, F0.w);
        u0.w = f2h2(F2.z, F2.w);
        u1.x = f2h2(F1.x, F1.y);
        u1.y = f2h2(F3.x, F3.y);
        u1.z = f2h2(F1.z, F1.w);
        u1.w = f2h2(F3.z, F3.w);
        uint4* dst = (uint4*)d;
        dst[2 * (size_t)j]     = u0;
        dst[2 * (size_t)j + 1] = u1;
    }
}

// ---------------------------------------------------------------------------
// FP16 GEMM body. BK=32 halves (2 k16 MMA steps per tile, NK=32), 3-stage
// cp.async ring, proven wait schedule. KSTRW=24 (≡24 mod 32): conflict-free
// uint2 fragment loads. BM=BN=128, 256 thr (8 warps 2x4), warp tile 64x32,
// 2 CTAs/SM.
// MODE 0: fp32 [M,C]. MODE 1: head-split kperm16 (g_q/g_k).
// MODE 2: head-split transposed [b,h,d,key], KEY dim kperm16 (g_v).
// ---------------------------------------------------------------------------
#define KSTRW 24                      // words per row (16 data + 8 pad)
#define STAGEW (128 * KSTRW)          // 3072 words per matrix stage
#define GEMM_SMEM_BYTES (3 * 2 * STAGEW * 4)   // 73,728 B

__device__ __forceinline__ void gemm_load_stage(
    unsigned* sA, unsigned* sB, const unsigned* __restrict__ X,
    const unsigned* __restrict__ W, int bm, int bn, int kt, int tid)
{
#pragma unroll
    for (int it = 0; it < 2; it++) {
        int f   = tid + it * 256;       // 0..511
        int row = f >> 2;               // 0..127
        int seg = (f & 3) * 4;          // word offset 0,4,8,12
        cp_async16(&sA[row * KSTRW + seg], &X[(size_t)(bm + row) * 512 + kt * 16 + seg]);
        cp_async16(&sB[row * KSTRW + seg], &W[(size_t)(bn + row) * 512 + kt * 16 + seg]);
    }
    cp_commit();
}

template <int MODE>
__device__ __forceinline__ void gemm_body(
    const unsigned* __restrict__ X, const unsigned* __restrict__ W,
    const float* __restrict__ bias, void* __restrict__ out,
    int Lrows, int bm, int bn, unsigned* gsm)
{
    unsigned* sAr = gsm;
    unsigned* sBr = gsm + 3 * STAGEW;

    const int tid  = threadIdx.x;
    const int wid  = tid >> 5;
    const int lane = tid & 31;
    const int wm   = (wid & 1) * 64;
    const int wn   = (wid >> 1) * 32;
    const int qr   = lane >> 2;
    const int ql   = lane & 3;

    float acc[4][4][4];
#pragma unroll
    for (int i = 0; i < 4; i++)
#pragma unroll
        for (int j = 0; j < 4; j++)
#pragma unroll
            for (int r = 0; r < 4; r++) acc[i][j][r] = 0.f;

    const int NK = C_DIM / 32;  // 32 k-tiles

    gemm_load_stage(sAr, sBr, X, W, bm, bn, 0, tid);
    gemm_load_stage(sAr + STAGEW, sBr + STAGEW, X, W, bm, bn, 1, tid);

    for (int kt = 0; kt < NK; kt++) {
        // Pending ⊆ {kt, kt+1}: wait until <=1 remains -> kt landed.
        if (kt + 1 < NK) cp_wait<1>(); else cp_wait<0>();
        __syncthreads();

        const int buf = kt % 3;
        if (kt + 2 < NK) {
            const int nb = (kt + 2) % 3;
            gemm_load_stage(sAr + nb * STAGEW, sBr + nb * STAGEW,
                            X, W, bm, bn, kt + 2, tid);
        }

        const unsigned* sA = sAr + buf * STAGEW;
        const unsigned* sB = sBr + buf * STAGEW;

#pragma unroll
        for (int ks = 0; ks < 2; ks++) {
            const int kwb = ks * 8;     // word base of this k16 step
            unsigned af[4][4], bf[4][2];
#pragma unroll
            for (int mi = 0; mi < 4; mi++) {
                int r0 = wm + mi * 16 + qr;
                uint2 lo = *(const uint2*)&sA[(r0)     * KSTRW + kwb + 2 * ql];
                uint2 hi = *(const uint2*)&sA[(r0 + 8) * KSTRW + kwb + 2 * ql];
                af[mi][0] = lo.x;
                af[mi][1] = hi.x;
                af[mi][2] = lo.y;
                af[mi][3] = hi.y;
            }
#pragma unroll
            for (int ni = 0; ni < 4; ni++) {
                int c0 = wn + ni * 8 + qr;
                uint2 bb = *(const uint2*)&sB[c0 * KSTRW + kwb + 2 * ql];
                bf[ni][0] = bb.x;
                bf[ni][1] = bb.y;
            }
#pragma unroll
            for (int mi = 0; mi < 4; mi++)
#pragma unroll
                for (int ni = 0; ni < 4; ni++)
                    mma_f16(acc[mi][ni], af[mi], bf[ni]);
        }
    }

    // ---- Epilogue ----
    if (MODE == 2) __syncthreads();   // gsm reused as transpose buffer
    __half* sT = (__half*)gsm;        // [128 dcol][136] halves (MODE 2)

#pragma unroll
    for (int mi = 0; mi < 4; mi++) {
#pragma unroll
        for (int ni = 0; ni < 4; ni++) {
            const int m0 = bm + wm + mi * 16 + qr;
            const int n0 = bn + wn + ni * 8 + 2 * ql;
            const float b0 = bias[n0], b1 = bias[n0 + 1];
            const float v00 = acc[mi][ni][0] + b0;
            const float v01 = acc[mi][ni][1] + b1;
            const float v10 = acc[mi][ni][2] + b0;
            const float v11 = acc[mi][ni][3] + b1;
            if (MODE == 0) {
                float* op = (float*)out;
                op[(size_t)m0 * C_DIM + n0]           = v00;
                op[(size_t)m0 * C_DIM + n0 + 1]       = v01;
                op[(size_t)(m0 + 8) * C_DIM + n0]     = v10;
                op[(size_t)(m0 + 8) * C_DIM + n0 + 1] = v11;
            } else if (MODE == 1) {
                unsigned* op = (unsigned*)out;
                const int h   = n0 >> 6;
                const int d   = n0 & 63;
                const int wrd = kp16_word(d);
                const int bz  = m0 / Lrows;
                const int l   = m0 - bz * Lrows;
                op[(((size_t)(bz * H_HEADS + h) * Lrows) + l) * 32 + wrd] = f2h2(v00, v01);
                const int bz2 = (m0 + 8) / Lrows;
                const int l2  = (m0 + 8) - bz2 * Lrows;
                op[(((size_t)(bz2 * H_HEADS + h) * Lrows) + l2) * 32 + wrd] = f2h2(v10, v11);
            } else {
                // MODE 2: stage into [dcol][key] with kperm16 on the key index
                const int jc = wn + ni * 8 + 2 * ql;
                const int kl = wm + mi * 16 + qr;
                sT[(jc)     * 136 + kp16_pos(kl)]     = __float2half_rn(v00);
                sT[(jc + 1) * 136 + kp16_pos(kl)]     = __float2half_rn(v01);
                sT[(jc)     * 136 + kp16_pos(kl + 8)] = __float2half_rn(v10);
                sT[(jc + 1) * 136 + kp16_pos(kl + 8)] = __float2half_rn(v11);
            }
        }
    }

    if (MODE == 2) {
        __syncthreads();
        const int bz = bm / Lrows;           // Lrows == LK
        const int l0 = bm - bz * Lrows;
        unsigned* op = (unsigned*)out;
#pragma unroll
        for (int p = 0; p < 8; p++) {
            int c   = tid + p * 256;          // 0..2047
            int j   = c >> 4;                 // local d col
            int seg = c & 15;                 // 16 uint4 per 128-key row
            uint4 v = *(const uint4*)&sT[j * 136 + seg * 8];
            size_t dstw = (size_t)(bz * 1024 + bn + j) * (LK / 2) + (l0 >> 1) + seg * 4;
            *(uint4*)&op[dstw] = v;
        }
    }
}

// Fused Q/K/V projections: 1152 CTA tiles.
__global__ __launch_bounds__(256, 2)
void qkv_proj_kernel(const float* __restrict__ Wq_b, const float* __restrict__ Wk_b,
                     const float* __restrict__ Wv_b)
{
    extern __shared__ unsigned gsm[];
    int t = blockIdx.x;
    if (t < 512) {
        const int bm = (t >> 3) * 128, bn = (t & 7) * 128;
        gemm_body<1>(g_xk, g_wt + 1 * C_DIM * (C_DIM / 2), Wk_b, g_k, LK, bm, bn, gsm);
    } else if (t < 1024) {
        t -= 512;
        const int bm = (t >> 3) * 128, bn = (t & 7) * 128;
        gemm_body<2>(g_xv, g_wt + 2 * C_DIM * (C_DIM / 2), Wv_b, g_v, LK, bm, bn, gsm);
    } else {
        t -= 1024;
        const int bm = (t >> 3) * 128, bn = (t & 7) * 128;
        gemm_body<1>(g_xq, g_wt, Wq_b, g_q, LQ, bm, bn, gsm);
    }
}

__global__ __launch_bounds__(256, 2)
void oproj_kernel(const float* __restrict__ Wo_b, float* __restrict__ out)
{
    extern __shared__ unsigned gsm[];
    const int bm = blockIdx.y * 128;
    const int bn = blockIdx.x * 128;
    gemm_body<0>(g_ctx, g_wt + 3 * C_DIM * (C_DIM / 2), Wo_b, out, 1, bm, bn, gsm);
}

// ---------------------------------------------------------------------------
// Flash attention (fp16). QSTRW=40 (≡8 mod 32): conflict-free uint2 fragment
// loads for uQ, uK AND key-permuted uV (PV B-frag = one LDS.64). f32-exp
// softmax; P packed to half2 as PV A-frags. 2 CTAs/SM, 4 syncs/chunk.
// ---------------------------------------------------------------------------
#define QT 128
#define KCH 64
#define QSTRW 40    // words/row (32 data + 8 pad); stride ≡ 8 (mod 32)
#define FLASH_SMEM_WORDS (QT * QSTRW + KCH * QSTRW + D_HEAD * QSTRW + KCH)
#define FLASH_SMEM_BYTES (FLASH_SMEM_WORDS * 4)   // 41,216 B
#define LOG2E 1.4426950408889634f

__global__ __launch_bounds__(256, 2)
void flash_kernel(const float* __restrict__ biasAll)
{
    extern __shared__ unsigned smu[];
    unsigned* uQ    = smu;                        // [128 q][40w]
    unsigned* uK    = uQ + QT * QSTRW;            // [64 key][40w]
    unsigned* uV    = uK + KCH * QSTRW;           // [64 d][40w] key-permuted
    float*    fBias = (float*)(uV + D_HEAD * QSTRW);  // [64]

    const int tid  = threadIdx.x;
    const int w    = tid >> 5;
    const int lane = tid & 31;
    const int qr   = lane >> 2;
    const int ql   = lane & 3;
    const int q0   = blockIdx.x * QT;
    const int h    = blockIdx.y;
    const int b    = blockIdx.z;

    const unsigned* qp = g_q + (size_t)(b * H_HEADS + h) * LQ * 32;
    const unsigned* kp = g_k + (size_t)(b * H_HEADS + h) * LK * 32;
    const unsigned* vp = g_v + (size_t)(b * H_HEADS + h) * D_HEAD * (LK / 2);
    const float*    bp = biasAll + (size_t)b * LK;

    // ---- prologue: group A = {Q, K0, bias0}; group B = {V0} ----
#pragma unroll
    for (int it = 0; it < 4; it++) {
        int f = tid + it * 256;
        int row = f >> 3;
        int seg = (f & 7) * 4;
        cp_async16(&uQ[row * QSTRW + seg], &qp[(size_t)(q0 + row) * 32 + seg]);
    }
#pragma unroll
    for (int it = 0; it < 2; it++) {
        int f = tid + it * 256;
        int row = f >> 3;
        int seg = (f & 7) * 4;
        cp_async16(&uK[row * QSTRW + seg], &kp[(size_t)row * 32 + seg]);
    }
    if (tid < 16) cp_async16(&fBias[tid * 4], &bp[tid * 4]);
    cp_commit();
#pragma unroll
    for (int it = 0; it < 2; it++) {
        int f = tid + it * 256;
        int d = f >> 3;
        int seg = (f & 7) * 4;
        cp_async16(&uV[d * QSTRW + seg], &vp[(size_t)d * (LK / 2) + seg]);
    }
    cp_commit();

    float o[8][4];
#pragma unroll
    for (int ni = 0; ni < 8; ni++)
#pragma unroll
        for (int r = 0; r < 4; r++) o[ni][r] = 0.f;

    float row_m[2] = {-1e30f, -1e30f};
    float row_l[2] = {0.f, 0.f};
    const float scl = 0.125f * LOG2E;
    const int r0 = w * 16 + qr;

    const int NCH = LK / KCH;  // 64
    for (int i = 0; i < NCH; i++) {
        const int kc0 = i * KCH;

        cp_wait<1>();   // pending {K_i, V_i} -> K_i (+Q,bias) landed
        if (tid < 16) {
            float4 bv = *(float4*)&fBias[tid * 4];
            bv.x *= LOG2E; bv.y *= LOG2E; bv.z *= LOG2E; bv.w *= LOG2E;
            *(float4*)&fBias[tid * 4] = bv;
        }
        __syncthreads();   // #1: K + bias visible

        // ---- S = Q @ K^T ----
        float s[8][4];
#pragma unroll
        for (int ni = 0; ni < 8; ni++)
#pragma unroll
            for (int r = 0; r < 4; r++) s[ni][r] = 0.f;

#pragma unroll
        for (int kk = 0; kk < 4; kk++) {
            const int kwb = kk * 8;
            uint2 aLo = *(const uint2*)&uQ[(r0)     * QSTRW + kwb + 2 * ql];
            uint2 aHi = *(const uint2*)&uQ[(r0 + 8) * QSTRW + kwb + 2 * ql];
            unsigned af[4];
            af[0] = aLo.x;
            af[1] = aHi.x;
            af[2] = aLo.y;
            af[3] = aHi.y;
#pragma unroll
            for (int ni = 0; ni < 8; ni++) {
                uint2 bb = *(const uint2*)&uK[(ni * 8 + qr) * QSTRW + kwb + 2 * ql];
                unsigned bf[2];
                bf[0] = bb.x;
                bf[1] = bb.y;
                mma_f16(s[ni], af, bf);
            }
        }

#pragma unroll
        for (int ni = 0; ni < 8; ni++) {
            const int c0 = ni * 8 + 2 * ql;
            const float b0 = fBias[c0], b1 = fBias[c0 + 1];
            s[ni][0] = fmaf(s[ni][0], scl, b0);
            s[ni][1] = fmaf(s[ni][1], scl, b1);
            s[ni][2] = fmaf(s[ni][2], scl, b0);
            s[ni][3] = fmaf(s[ni][3], scl, b1);
        }
        __syncthreads();   // #2: done with K + bias

        if (i + 1 < NCH) {
#pragma unroll
            for (int it = 0; it < 2; it++) {
                int f = tid + it * 256;
                int row = f >> 3;
                int seg = (f & 7) * 4;
                cp_async16(&uK[row * QSTRW + seg],
                           &kp[(size_t)(kc0 + KCH + row) * 32 + seg]);
            }
            if (tid < 16) cp_async16(&fBias[tid * 4], &bp[kc0 + KCH + tid * 4]);
            cp_commit();
        }

        // ---- online softmax (f32 exp) ----
#pragma unroll
        for (int half = 0; half < 2; half++) {
            float mx = -1e30f;
#pragma unroll
            for (int ni = 0; ni < 8; ni++)
                mx = fmaxf(mx, fmaxf(s[ni][2 * half], s[ni][2 * half + 1]));
            mx = fmaxf(mx, __shfl_xor_sync(0xffffffffu, mx, 1));
            mx = fmaxf(mx, __shfl_xor_sync(0xffffffffu, mx, 2));
            const float mnew  = fmaxf(row_m[half], mx);
            const float alpha = ex2f(row_m[half] - mnew);
            row_m[half] = mnew;
            float ls = 0.f;
#pragma unroll
            for (int ni = 0; ni < 8; ni++) {
                float e0 = ex2f(s[ni][2 * half]     - mnew);
                float e1 = ex2f(s[ni][2 * half + 1] - mnew);
                s[ni][2 * half]     = e0;
                s[ni][2 * half + 1] = e1;
                ls += e0 + e1;
            }
            ls += __shfl_xor_sync(0xffffffffu, ls, 1);
            ls += __shfl_xor_sync(0xffffffffu, ls, 2);
            row_l[half] = row_l[half] * alpha + ls;
#pragma unroll
            for (int ni = 0; ni < 8; ni++) {
                o[ni][2 * half]     *= alpha;
                o[ni][2 * half + 1] *= alpha;
            }
        }

        // pending {V_i, K_{i+1}} (or {V_i}) -> V_i landed
        if (i + 1 < NCH) cp_wait<1>(); else cp_wait<0>();
        __syncthreads();   // #3: V visible

        // ---- O += P @ V : key-permuted V -> B-frag is one LDS.64 ----
#pragma unroll
        for (int kk = 0; kk < 4; kk++) {
            unsigned af[4];
            af[0] = f2h2(s[2 * kk][0],     s[2 * kk][1]);
            af[1] = f2h2(s[2 * kk][2],     s[2 * kk][3]);
            af[2] = f2h2(s[2 * kk + 1][0], s[2 * kk + 1][1]);
            af[3] = f2h2(s[2 * kk + 1][2], s[2 * kk + 1][3]);
#pragma unroll
            for (int ni = 0; ni < 8; ni++) {
                uint2 bb = *(const uint2*)&uV[(ni * 8 + qr) * QSTRW + kk * 8 + 2 * ql];
                unsigned bf[2];
                bf[0] = bb.x;
                bf[1] = bb.y;
                mma_f16(o[ni], af, bf);
            }
        }
        __syncthreads();   // #4: done with V

        if (i + 1 < NCH) {
#pragma unroll
            for (int it = 0; it < 2; it++) {
                int f = tid + it * 256;
                int d = f >> 3;
                int seg = (f & 7) * 4;
                cp_async16(&uV[d * QSTRW + seg],
                           &vp[(size_t)d * (LK / 2) + ((kc0 + KCH) >> 1) + seg]);
            }
            cp_commit();
        }
    }

    // ---- normalize; write ctx fp16 kperm16-packed ----
    const float inv0 = __fdividef(1.f, row_l[0]);
    const float inv1 = __fdividef(1.f, row_l[1]);
    unsigned* ctx = g_ctx + (size_t)b * LQ * 512;
    const int rA = q0 + r0;
#pragma unroll
    for (int ni = 0; ni < 8; ni++) {
        const int col = h * 64 + ni * 8 + 2 * ql;
        const int wrd = kp16_word(col & 15) + ((col >> 4) << 3);
        ctx[(size_t)rA * 512 + wrd]       = f2h2(o[ni][0] * inv0, o[ni][1] * inv0);
        ctx[(size_t)(rA + 8) * 512 + wrd] = f2h2(o[ni][2] * inv1, o[ni][3] * inv1);
    }
}

// ---------------------------------------------------------------------------
// kernel_launch: 4 stream-ordered launches (graph-capturable, alloc-free)
// ---------------------------------------------------------------------------
extern "C" void kernel_launch(void* const* d_in, const int* in_sizes, int n_in,
                              void* d_out, int out_size)
{
    const float* Q      = (const float*)d_in[0];
    const float* K_in   = (const float*)d_in[1];
    const float* V_in   = (const float*)d_in[2];
    const float* V_bias = (const float*)d_in[3];
    const float* Wq_b   = (const float*)d_in[5];
    const float* Wk_b   = (const float*)d_in[7];
    const float* Wv_b   = (const float*)d_in[9];
    const float* Wo_b   = (const float*)d_in[11];

    cudaFuncSetAttribute(flash_kernel,
                         cudaFuncAttributeMaxDynamicSharedMemorySize, FLASH_SMEM_BYTES);
    cudaFuncSetAttribute(qkv_proj_kernel,
                         cudaFuncAttributeMaxDynamicSharedMemorySize, GEMM_SMEM_BYTES);
    cudaFuncSetAttribute(oproj_kernel,
                         cudaFuncAttributeMaxDynamicSharedMemorySize, GEMM_SMEM_BYTES);

    precvt_kernel<<<1184, 512>>>((const float4*)Q, (const float4*)K_in,
                                 (const float4*)V_in, (const float4*)d_in[4],
                                 (const float4*)d_in[6], (const float4*)d_in[8],
                                 (const float4*)d_in[10]);

    qkv_proj_kernel<<<1152, 256, GEMM_SMEM_BYTES>>>(Wq_b, Wk_b, Wv_b);

    flash_kernel<<<dim3(LQ / QT, H_HEADS, B_BATCH), 256, FLASH_SMEM_BYTES>>>(V_bias);

    oproj_kernel<<<dim3(C_DIM / 128, (B_BATCH * LQ) / 128), 256, GEMM_SMEM_BYTES>>>(
        Wo_b, (float*)d_out);
}

// round 17
// speedup vs baseline: 1.2998x; 1.0164x over previous
#include <cuda_runtime.h>
#include <cuda_fp16.h>
#include <cstdint>
#include <cstddef>

// ---------------------------------------------------------------------------
// Problem constants
// ---------------------------------------------------------------------------
#define C_DIM   1024
#define H_HEADS 16
#define D_HEAD  64
#define B_BATCH 2
#define LQ      1024
#define LK      4096

// ---------------------------------------------------------------------------
// Device scratch (allocation-free). All fp16 as unsigned half2 words.
// kperm16 within-16 groups: w0:(j0,j1) w1:(j8,j9) w2:(j2,j3) w3:(j10,j11)
// w4:(j4,j5) w5:(j12,j13) w6:(j6,j7) w7:(j14,j15)  -> fragment pairs adjacent.
// g_x*/g_wt/g_ctx: kperm16 along k/c. g_q/g_k: kperm16 along d.
// g_v: TRANSPOSED [b,h,d,key] with kperm16 along the KEY dim.
// ---------------------------------------------------------------------------
__device__ unsigned g_q  [B_BATCH * H_HEADS * LQ * (D_HEAD / 2)];
__device__ unsigned g_k  [B_BATCH * H_HEADS * LK * (D_HEAD / 2)];
__device__ unsigned g_v  [B_BATCH * H_HEADS * D_HEAD * (LK / 2)];
__device__ unsigned g_ctx[B_BATCH * LQ * (C_DIM / 2)];
__device__ unsigned g_xq [B_BATCH * LQ * (C_DIM / 2)];
__device__ unsigned g_xk [B_BATCH * LK * (C_DIM / 2)];
__device__ unsigned g_xv [B_BATCH * LK * (C_DIM / 2)];
__device__ unsigned g_wt [4 * C_DIM * (C_DIM / 2)];

// ---------------------------------------------------------------------------
// Helpers
// ---------------------------------------------------------------------------
__device__ __forceinline__ unsigned f2h2(float lo, float hi) {
    __half2 h = __floats2half2_rn(lo, hi);
    return *reinterpret_cast<unsigned*>(&h);
}
__device__ __forceinline__ float ex2f(float x) {
    float y;
    asm volatile("ex2.approx.f32 %0, %1;" : "=f"(y) : "f"(x));
    return y;
}
__device__ __forceinline__ unsigned h2exp2(unsigned x) {
    unsigned y;
    asm volatile("ex2.approx.f16x2 %0, %1;" : "=r"(y) : "r"(x));
    return y;
}
// half2-word index (within a 16-elem group row) for even element d
__device__ __forceinline__ int kp16_word(int d) {
    return ((d >> 4) << 3) + 2 * ((d & 7) >> 1) + ((d >> 3) & 1);
}
// permuted half position for element j under kperm16 (within full row)
__device__ __forceinline__ int kp16_pos(int j) {
    int g = j & ~15;
    int p = j & 15;
    int w = 2 * ((p & 7) >> 1) + ((p >> 3) & 1);
    return g + 2 * w + (p & 1);
}
// D(16x8,f32) += A(16x16 f16 row) * B(16x8 f16 col)
__device__ __forceinline__ void mma_f16(float c[4], const unsigned a[4], const unsigned b[2]) {
    asm volatile(
        "mma.sync.aligned.m16n8k16.row.col.f32.f16.f16.f32 "
        "{%0,%1,%2,%3}, {%4,%5,%6,%7}, {%8,%9}, {%0,%1,%2,%3};"
        : "+f"(c[0]), "+f"(c[1]), "+f"(c[2]), "+f"(c[3])
        : "r"(a[0]), "r"(a[1]), "r"(a[2]), "r"(a[3]), "r"(b[0]), "r"(b[1]));
}
__device__ __forceinline__ void cp_async16(void* smem, const void* gmem) {
    unsigned sa = (unsigned)__cvta_generic_to_shared(smem);
    asm volatile("cp.async.ca.shared.global [%0], [%1], 16;" :: "r"(sa), "l"(gmem));
}
__device__ __forceinline__ void cp_commit() { asm volatile("cp.async.commit_group;"); }
template <int N>
__device__ __forceinline__ void cp_wait() { asm volatile("cp.async.wait_group %0;" :: "n"(N)); }

// ---------------------------------------------------------------------------
// Pre-convert: fp32 -> fp16, kperm16-packed. One thread per 16-float group.
// ---------------------------------------------------------------------------
#define G16_Q (B_BATCH * LQ * C_DIM / 16)
#define G16_K (B_BATCH * LK * C_DIM / 16)
#define G16_W (C_DIM * C_DIM / 16)

__global__ __launch_bounds__(512)
void precvt_kernel(const float4* __restrict__ Q, const float4* __restrict__ K,
                   const float4* __restrict__ V, const float4* __restrict__ Wq,
                   const float4* __restrict__ Wk, const float4* __restrict__ Wv,
                   const float4* __restrict__ Wo)
{
    const int total = G16_Q + 2 * G16_K + 4 * G16_W;
    for (int g = blockIdx.x * blockDim.x + threadIdx.x; g < total;
         g += gridDim.x * blockDim.x) {
        const float4* s;
        unsigned* d;
        int j = g;
        if (j < G16_Q)                 { s = Q; d = g_xq; }
        else if ((j -= G16_Q) < G16_K) { s = K; d = g_xk; }
        else if ((j -= G16_K) < G16_K) { s = V; d = g_xv; }
        else {
            j -= G16_K;
            int w = j / G16_W;
            j -= w * G16_W;
            s = (w == 0) ? Wq : (w == 1) ? Wk : (w == 2) ? Wv : Wo;
            d = g_wt + (size_t)w * (C_DIM * (C_DIM / 2));
        }
        const float4* f4 = s + (size_t)j * 4;
        float4 F0 = f4[0], F1 = f4[1], F2 = f4[2], F3 = f4[3];
        uint4 u0, u1;
        u0.x = f2h2(F0.x, F0.y);
        u0.y = f2h2(F2.x, F2.y);
        u0.z = f2h2(F0.z, F0.w);
        u0.w = f2h2(F2.z, F2.w);
        u1.x = f2h2(F1.x, F1.y);
        u1.y = f2h2(F3.x, F3.y);
        u1.z = f2h2(F1.z, F1.w);
        u1.w = f2h2(F3.z, F3.w);
        uint4* dst = (uint4*)d;
        dst[2 * (size_t)j]     = u0;
        dst[2 * (size_t)j + 1] = u1;
    }
}

// ---------------------------------------------------------------------------
// FP16 GEMM body. BK=32 halves (2 k16 MMA steps per tile, NK=32), 3-stage
// cp.async ring, proven wait schedule. KSTRW=24 (≡24 mod 32): conflict-free
// uint2 fragment loads. BM=BN=128, 256 thr (8 warps 2x4), warp tile 64x32,
// 2 CTAs/SM.
// MODE 0: fp32 [M,C]. MODE 1: head-split kperm16 (g_q/g_k).
// MODE 2: head-split transposed [b,h,d,key], KEY dim kperm16 (g_v).
// ---------------------------------------------------------------------------
#define KSTRW 24                      // words per row (16 data + 8 pad)
#define STAGEW (128 * KSTRW)          // 3072 words per matrix stage
#define GEMM_SMEM_BYTES (3 * 2 * STAGEW * 4)   // 73,728 B

__device__ __forceinline__ void gemm_load_stage(
    unsigned* sA, unsigned* sB, const unsigned* __restrict__ X,
    const unsigned* __restrict__ W, int bm, int bn, int kt, int tid)
{
#pragma unroll
    for (int it = 0; it < 2; it++) {
        int f   = tid + it * 256;       // 0..511
        int row = f >> 2;               // 0..127
        int seg = (f & 3) * 4;          // word offset 0,4,8,12
        cp_async16(&sA[row * KSTRW + seg], &X[(size_t)(bm + row) * 512 + kt * 16 + seg]);
        cp_async16(&sB[row * KSTRW + seg], &W[(size_t)(bn + row) * 512 + kt * 16 + seg]);
    }
    cp_commit();
}

template <int MODE>
__device__ __forceinline__ void gemm_body(
    const unsigned* __restrict__ X, const unsigned* __restrict__ W,
    const float* __restrict__ bias, void* __restrict__ out,
    int Lrows, int bm, int bn, unsigned* gsm)
{
    unsigned* sAr = gsm;
    unsigned* sBr = gsm + 3 * STAGEW;

    const int tid  = threadIdx.x;
    const int wid  = tid >> 5;
    const int lane = tid & 31;
    const int wm   = (wid & 1) * 64;
    const int wn   = (wid >> 1) * 32;
    const int qr   = lane >> 2;
    const int ql   = lane & 3;

    float acc[4][4][4];
#pragma unroll
    for (int i = 0; i < 4; i++)
#pragma unroll
        for (int j = 0; j < 4; j++)
#pragma unroll
            for (int r = 0; r < 4; r++) acc[i][j][r] = 0.f;

    const int NK = C_DIM / 32;  // 32 k-tiles

    gemm_load_stage(sAr, sBr, X, W, bm, bn, 0, tid);
    gemm_load_stage(sAr + STAGEW, sBr + STAGEW, X, W, bm, bn, 1, tid);

    for (int kt = 0; kt < NK; kt++) {
        // Pending ⊆ {kt, kt+1}: wait until <=1 remains -> kt landed.
        if (kt + 1 < NK) cp_wait<1>(); else cp_wait<0>();
        __syncthreads();

        const int buf = kt % 3;
        if (kt + 2 < NK) {
            const int nb = (kt + 2) % 3;
            gemm_load_stage(sAr + nb * STAGEW, sBr + nb * STAGEW,
                            X, W, bm, bn, kt + 2, tid);
        }

        const unsigned* sA = sAr + buf * STAGEW;
        const unsigned* sB = sBr + buf * STAGEW;

#pragma unroll
        for (int ks = 0; ks < 2; ks++) {
            const int kwb = ks * 8;     // word base of this k16 step
            unsigned af[4][4], bf[4][2];
#pragma unroll
            for (int mi = 0; mi < 4; mi++) {
                int r0 = wm + mi * 16 + qr;
                uint2 lo = *(const uint2*)&sA[(r0)     * KSTRW + kwb + 2 * ql];
                uint2 hi = *(const uint2*)&sA[(r0 + 8) * KSTRW + kwb + 2 * ql];
                af[mi][0] = lo.x;
                af[mi][1] = hi.x;
                af[mi][2] = lo.y;
                af[mi][3] = hi.y;
            }
#pragma unroll
            for (int ni = 0; ni < 4; ni++) {
                int c0 = wn + ni * 8 + qr;
                uint2 bb = *(const uint2*)&sB[c0 * KSTRW + kwb + 2 * ql];
                bf[ni][0] = bb.x;
                bf[ni][1] = bb.y;
            }
#pragma unroll
            for (int mi = 0; mi < 4; mi++)
#pragma unroll
                for (int ni = 0; ni < 4; ni++)
                    mma_f16(acc[mi][ni], af[mi], bf[ni]);
        }
    }

    // ---- Epilogue ----
    if (MODE == 2) __syncthreads();   // gsm reused as transpose buffer
    __half* sT = (__half*)gsm;        // [128 dcol][136] halves (MODE 2)

#pragma unroll
    for (int mi = 0; mi < 4; mi++) {
#pragma unroll
        for (int ni = 0; ni < 4; ni++) {
            const int m0 = bm + wm + mi * 16 + qr;
            const int n0 = bn + wn + ni * 8 + 2 * ql;
            const float b0 = bias[n0], b1 = bias[n0 + 1];
            const float v00 = acc[mi][ni][0] + b0;
            const float v01 = acc[mi][ni][1] + b1;
            const float v10 = acc[mi][ni][2] + b0;
            const float v11 = acc[mi][ni][3] + b1;
            if (MODE == 0) {
                float* op = (float*)out;
                op[(size_t)m0 * C_DIM + n0]           = v00;
                op[(size_t)m0 * C_DIM + n0 + 1]       = v01;
                op[(size_t)(m0 + 8) * C_DIM + n0]     = v10;
                op[(size_t)(m0 + 8) * C_DIM + n0 + 1] = v11;
            } else if (MODE == 1) {
                unsigned* op = (unsigned*)out;
                const int h   = n0 >> 6;
                const int d   = n0 & 63;
                const int wrd = kp16_word(d);
                const int bz  = m0 / Lrows;
                const int l   = m0 - bz * Lrows;
                op[(((size_t)(bz * H_HEADS + h) * Lrows) + l) * 32 + wrd] = f2h2(v00, v01);
                const int bz2 = (m0 + 8) / Lrows;
                const int l2  = (m0 + 8) - bz2 * Lrows;
                op[(((size_t)(bz2 * H_HEADS + h) * Lrows) + l2) * 32 + wrd] = f2h2(v10, v11);
            } else {
                // MODE 2: stage into [dcol][key] with kperm16 on the key index
                const int jc = wn + ni * 8 + 2 * ql;
                const int kl = wm + mi * 16 + qr;
                sT[(jc)     * 136 + kp16_pos(kl)]     = __float2half_rn(v00);
                sT[(jc + 1) * 136 + kp16_pos(kl)]     = __float2half_rn(v01);
                sT[(jc)     * 136 + kp16_pos(kl + 8)] = __float2half_rn(v10);
                sT[(jc + 1) * 136 + kp16_pos(kl + 8)] = __float2half_rn(v11);
            }
        }
    }

    if (MODE == 2) {
        __syncthreads();
        const int bz = bm / Lrows;           // Lrows == LK
        const int l0 = bm - bz * Lrows;
        unsigned* op = (unsigned*)out;
#pragma unroll
        for (int p = 0; p < 8; p++) {
            int c   = tid + p * 256;          // 0..2047
            int j   = c >> 4;                 // local d col
            int seg = c & 15;                 // 16 uint4 per 128-key row
            uint4 v = *(const uint4*)&sT[j * 136 + seg * 8];
            size_t dstw = (size_t)(bz * 1024 + bn + j) * (LK / 2) + (l0 >> 1) + seg * 4;
            *(uint4*)&op[dstw] = v;
        }
    }
}

// Fused Q/K/V projections: 1152 CTA tiles.
__global__ __launch_bounds__(256, 2)
void qkv_proj_kernel(const float* __restrict__ Wq_b, const float* __restrict__ Wk_b,
                     const float* __restrict__ Wv_b)
{
    extern __shared__ unsigned gsm[];
    int t = blockIdx.x;
    if (t < 512) {
        const int bm = (t >> 3) * 128, bn = (t & 7) * 128;
        gemm_body<1>(g_xk, g_wt + 1 * C_DIM * (C_DIM / 2), Wk_b, g_k, LK, bm, bn, gsm);
    } else if (t < 1024) {
        t -= 512;
        const int bm = (t >> 3) * 128, bn = (t & 7) * 128;
        gemm_body<2>(g_xv, g_wt + 2 * C_DIM * (C_DIM / 2), Wv_b, g_v, LK, bm, bn, gsm);
    } else {
        t -= 1024;
        const int bm = (t >> 3) * 128, bn = (t & 7) * 128;
        gemm_body<1>(g_xq, g_wt, Wq_b, g_q, LQ, bm, bn, gsm);
    }
}

__global__ __launch_bounds__(256, 2)
void oproj_kernel(const float* __restrict__ Wo_b, float* __restrict__ out)
{
    extern __shared__ unsigned gsm[];
    const int bm = blockIdx.y * 128;
    const int bn = blockIdx.x * 128;
    gemm_body<0>(g_ctx, g_wt + 3 * C_DIM * (C_DIM / 2), Wo_b, out, 1, bm, bn, gsm);
}

// ---------------------------------------------------------------------------
// Flash attention (fp16). QSTRW=40 (≡8 mod 32): conflict-free uint2 fragment
// loads for uQ, uK AND key-permuted uV (PV B-frag = one LDS.64).
// Softmax exp via ex2.approx.f16x2 (halved MUFU): P computed directly as
// half2 PV A-fragments; ls accumulated in fp32 from the actual fp16 P values.
// 2 CTAs/SM, 4 syncs/chunk.
// ---------------------------------------------------------------------------
#define QT 128
#define KCH 64
#define QSTRW 40    // words/row (32 data + 8 pad); stride ≡ 8 (mod 32)
#define FLASH_SMEM_WORDS (QT * QSTRW + KCH * QSTRW + D_HEAD * QSTRW + KCH)
#define FLASH_SMEM_BYTES (FLASH_SMEM_WORDS * 4)   // 41,216 B
#define LOG2E 1.4426950408889634f

__global__ __launch_bounds__(256, 2)
void flash_kernel(const float* __restrict__ biasAll)
{
    extern __shared__ unsigned smu[];
    unsigned* uQ    = smu;                        // [128 q][40w]
    unsigned* uK    = uQ + QT * QSTRW;            // [64 key][40w]
    unsigned* uV    = uK + KCH * QSTRW;           // [64 d][40w] key-permuted
    float*    fBias = (float*)(uV + D_HEAD * QSTRW);  // [64]

    const int tid  = threadIdx.x;
    const int w    = tid >> 5;
    const int lane = tid & 31;
    const int qr   = lane >> 2;
    const int ql   = lane & 3;
    const int q0   = blockIdx.x * QT;
    const int h    = blockIdx.y;
    const int b    = blockIdx.z;

    const unsigned* qp = g_q + (size_t)(b * H_HEADS + h) * LQ * 32;
    const unsigned* kp = g_k + (size_t)(b * H_HEADS + h) * LK * 32;
    const unsigned* vp = g_v + (size_t)(b * H_HEADS + h) * D_HEAD * (LK / 2);
    const float*    bp = biasAll + (size_t)b * LK;

    // ---- prologue: group A = {Q, K0, bias0}; group B = {V0} ----
#pragma unroll
    for (int it = 0; it < 4; it++) {
        int f = tid + it * 256;
        int row = f >> 3;
        int seg = (f & 7) * 4;
        cp_async16(&uQ[row * QSTRW + seg], &qp[(size_t)(q0 + row) * 32 + seg]);
    }
#pragma unroll
    for (int it = 0; it < 2; it++) {
        int f = tid + it * 256;
        int row = f >> 3;
        int seg = (f & 7) * 4;
        cp_async16(&uK[row * QSTRW + seg], &kp[(size_t)row * 32 + seg]);
    }
    if (tid < 16) cp_async16(&fBias[tid * 4], &bp[tid * 4]);
    cp_commit();
#pragma unroll
    for (int it = 0; it < 2; it++) {
        int f = tid + it * 256;
        int d = f >> 3;
        int seg = (f & 7) * 4;
        cp_async16(&uV[d * QSTRW + seg], &vp[(size_t)d * (LK / 2) + seg]);
    }
    cp_commit();

    float o[8][4];
#pragma unroll
    for (int ni = 0; ni < 8; ni++)
#pragma unroll
        for (int r = 0; r < 4; r++) o[ni][r] = 0.f;

    float row_m[2] = {-1e30f, -1e30f};
    float row_l[2] = {0.f, 0.f};
    const float scl = 0.125f * LOG2E;
    const int r0 = w * 16 + qr;

    const int NCH = LK / KCH;  // 64
    for (int i = 0; i < NCH; i++) {
        const int kc0 = i * KCH;

        cp_wait<1>();   // pending {K_i, V_i} -> K_i (+Q,bias) landed
        if (tid < 16) {
            float4 bv = *(float4*)&fBias[tid * 4];
            bv.x *= LOG2E; bv.y *= LOG2E; bv.z *= LOG2E; bv.w *= LOG2E;
            *(float4*)&fBias[tid * 4] = bv;
        }
        __syncthreads();   // #1: K + bias visible

        // ---- S = Q @ K^T ----
        float s[8][4];
#pragma unroll
        for (int ni = 0; ni < 8; ni++)
#pragma unroll
            for (int r = 0; r < 4; r++) s[ni][r] = 0.f;

#pragma unroll
        for (int kk = 0; kk < 4; kk++) {
            const int kwb = kk * 8;
            uint2 aLo = *(const uint2*)&uQ[(r0)     * QSTRW + kwb + 2 * ql];
            uint2 aHi = *(const uint2*)&uQ[(r0 + 8) * QSTRW + kwb + 2 * ql];
            unsigned af[4];
            af[0] = aLo.x;
            af[1] = aHi.x;
            af[2] = aLo.y;
            af[3] = aHi.y;
#pragma unroll
            for (int ni = 0; ni < 8; ni++) {
                uint2 bb = *(const uint2*)&uK[(ni * 8 + qr) * QSTRW + kwb + 2 * ql];
                unsigned bf[2];
                bf[0] = bb.x;
                bf[1] = bb.y;
                mma_f16(s[ni], af, bf);
            }
        }

#pragma unroll
        for (int ni = 0; ni < 8; ni++) {
            const int c0 = ni * 8 + 2 * ql;
            const float b0 = fBias[c0], b1 = fBias[c0 + 1];
            s[ni][0] = fmaf(s[ni][0], scl, b0);
            s[ni][1] = fmaf(s[ni][1], scl, b1);
            s[ni][2] = fmaf(s[ni][2], scl, b0);
            s[ni][3] = fmaf(s[ni][3], scl, b1);
        }
        __syncthreads();   // #2: done with K + bias

        if (i + 1 < NCH) {
#pragma unroll
            for (int it = 0; it < 2; it++) {
                int f = tid + it * 256;
                int row = f >> 3;
                int seg = (f & 7) * 4;
                cp_async16(&uK[row * QSTRW + seg],
                           &kp[(size_t)(kc0 + KCH + row) * 32 + seg]);
            }
            if (tid < 16) cp_async16(&fBias[tid * 4], &bp[kc0 + KCH + tid * 4]);
            cp_commit();
        }

        // ---- online softmax; P produced directly as half2 (PV A-frags) ----
        unsigned p2[2][8];
#pragma unroll
        for (int half = 0; half < 2; half++) {
            float mx = -1e30f;
#pragma unroll
            for (int ni = 0; ni < 8; ni++)
                mx = fmaxf(mx, fmaxf(s[ni][2 * half], s[ni][2 * half + 1]));
            mx = fmaxf(mx, __shfl_xor_sync(0xffffffffu, mx, 1));
            mx = fmaxf(mx, __shfl_xor_sync(0xffffffffu, mx, 2));
            const float mnew  = fmaxf(row_m[half], mx);
            const float alpha = ex2f(row_m[half] - mnew);
            row_m[half] = mnew;
            float ls = 0.f;
#pragma unroll
            for (int ni = 0; ni < 8; ni++) {
                unsigned t = f2h2(s[ni][2 * half] - mnew, s[ni][2 * half + 1] - mnew);
                unsigned p = h2exp2(t);
                p2[half][ni] = p;
                float2 pf = __half22float2(*reinterpret_cast<__half2*>(&p));
                ls += pf.x + pf.y;
            }
            ls += __shfl_xor_sync(0xffffffffu, ls, 1);
            ls += __shfl_xor_sync(0xffffffffu, ls, 2);
            row_l[half] = row_l[half] * alpha + ls;
#pragma unroll
            for (int ni = 0; ni < 8; ni++) {
                o[ni][2 * half]     *= alpha;
                o[ni][2 * half + 1] *= alpha;
            }
        }

        // pending {V_i, K_{i+1}} (or {V_i}) -> V_i landed
        if (i + 1 < NCH) cp_wait<1>(); else cp_wait<0>();
        __syncthreads();   // #3: V visible

        // ---- O += P @ V : key-permuted V -> B-frag is one LDS.64 ----
#pragma unroll
        for (int kk = 0; kk < 4; kk++) {
            unsigned af[4];
            af[0] = p2[0][2 * kk];
            af[1] = p2[1][2 * kk];
            af[2] = p2[0][2 * kk + 1];
            af[3] = p2[1][2 * kk + 1];
#pragma unroll
            for (int ni = 0; ni < 8; ni++) {
                uint2 bb = *(const uint2*)&uV[(ni * 8 + qr) * QSTRW + kk * 8 + 2 * ql];
                unsigned bf[2];
                bf[0] = bb.x;
                bf[1] = bb.y;
                mma_f16(o[ni], af, bf);
            }
        }
        __syncthreads();   // #4: done with V

        if (i + 1 < NCH) {
#pragma unroll
            for (int it = 0; it < 2; it++) {
                int f = tid + it * 256;
                int d = f >> 3;
                int seg = (f & 7) * 4;
                cp_async16(&uV[d * QSTRW + seg],
                           &vp[(size_t)d * (LK / 2) + ((kc0 + KCH) >> 1) + seg]);
            }
            cp_commit();
        }
    }

    // ---- normalize; write ctx fp16 kperm16-packed ----
    const float inv0 = __fdividef(1.f, row_l[0]);
    const float inv1 = __fdividef(1.f, row_l[1]);
    unsigned* ctx = g_ctx + (size_t)b * LQ * 512;
    const int rA = q0 + r0;
#pragma unroll
    for (int ni = 0; ni < 8; ni++) {
        const int col = h * 64 + ni * 8 + 2 * ql;
        const int wrd = kp16_word(col & 15) + ((col >> 4) << 3);
        ctx[(size_t)rA * 512 + wrd]       = f2h2(o[ni][0] * inv0, o[ni][1] * inv0);
        ctx[(size_t)(rA + 8) * 512 + wrd] = f2h2(o[ni][2] * inv1, o[ni][3] * inv1);
    }
}

// ---------------------------------------------------------------------------
// kernel_launch: 4 stream-ordered launches (graph-capturable, alloc-free)
// ---------------------------------------------------------------------------
extern "C" void kernel_launch(void* const* d_in, const int* in_sizes, int n_in,
                              void* d_out, int out_size)
{
    const float* Q      = (const float*)d_in[0];
    const float* K_in   = (const float*)d_in[1];
    const float* V_in   = (const float*)d_in[2];
    const float* V_bias = (const float*)d_in[3];
    const float* Wq_b   = (const float*)d_in[5];
    const float* Wk_b   = (const float*)d_in[7];
    const float* Wv_b   = (const float*)d_in[9];
    const float* Wo_b   = (const float*)d_in[11];

    cudaFuncSetAttribute(flash_kernel,
                         cudaFuncAttributeMaxDynamicSharedMemorySize, FLASH_SMEM_BYTES);
    cudaFuncSetAttribute(qkv_proj_kernel,
                         cudaFuncAttributeMaxDynamicSharedMemorySize, GEMM_SMEM_BYTES);
    cudaFuncSetAttribute(oproj_kernel,
                         cudaFuncAttributeMaxDynamicSharedMemorySize, GEMM_SMEM_BYTES);

    precvt_kernel<<<1184, 512>>>((const float4*)Q, (const float4*)K_in,
                                 (const float4*)V_in, (const float4*)d_in[4],
                                 (const float4*)d_in[6], (const float4*)d_in[8],
                                 (const float4*)d_in[10]);

    qkv_proj_kernel<<<1152, 256, GEMM_SMEM_BYTES>>>(Wq_b, Wk_b, Wv_b);

    flash_kernel<<<dim3(LQ / QT, H_HEADS, B_BATCH), 256, FLASH_SMEM_BYTES>>>(V_bias);

    oproj_kernel<<<dim3(C_DIM / 128, (B_BATCH * LQ) / 128), 256, GEMM_SMEM_BYTES>>>(
        Wo_b, (float*)d_out);
}